// round 1
// baseline (speedup 1.0000x reference)
#include <cuda_runtime.h>
#include <cuda_bf16.h>

// Problem constants
#define NNODES 50000
#define NEDGES 800000
#define IN_DIM 256
#define HDIM   128
#define H2DIM  64
#define ODIM   32
#define KHOPS  5
#define EPS    1e-5f

// ---------------------------------------------------------------------------
// Scratch (device globals; no allocation allowed)
// ---------------------------------------------------------------------------
__device__ float gB0[NNODES * HDIM];
__device__ float gB1[NNODES * HDIM];
__device__ float gB2[NNODES * HDIM];
__device__ float gFz[NNODES * HDIM];
__device__ float gWsum[NNODES];
__device__ float gEN[NEDGES];
__device__ float gSw[8];

// ---------------------------------------------------------------------------
// Tiled fp32 GEMM  out = relu(bn(A@W + b)) [+ ident]
// BM=64, BN=128(full), BK=16, 256 threads, 8x4 register tile
// ---------------------------------------------------------------------------
template <int KDIM, bool RES>
__global__ void gemm_bn_relu(const float* __restrict__ A,
                             const float* __restrict__ W,
                             const float* __restrict__ bias,
                             const float* __restrict__ g,
                             const float* __restrict__ be,
                             const float* __restrict__ m,
                             const float* __restrict__ v,
                             const float* __restrict__ ident,
                             float* __restrict__ out, int M) {
    __shared__ float  As[64][17];
    __shared__ float4 Bs[16][32];
    const int tid = threadIdx.x;
    const int rowBase = blockIdx.x * 64;
    const int cg = tid & 31;   // col group: cols cg*4 .. cg*4+3
    const int rg = tid >> 5;   // row group: rows rg*8 .. rg*8+7

    float acc[8][4];
#pragma unroll
    for (int i = 0; i < 8; i++)
#pragma unroll
        for (int j = 0; j < 4; j++) acc[i][j] = 0.f;

    for (int k0 = 0; k0 < KDIM; k0 += 16) {
        // Load A tile 64x16 (float4 per thread)
        {
            int r = tid >> 2, c4 = tid & 3;
            float4 val = make_float4(0.f, 0.f, 0.f, 0.f);
            if (rowBase + r < M)
                val = *(const float4*)(A + (size_t)(rowBase + r) * KDIM + k0 + c4 * 4);
            As[r][c4 * 4 + 0] = val.x; As[r][c4 * 4 + 1] = val.y;
            As[r][c4 * 4 + 2] = val.z; As[r][c4 * 4 + 3] = val.w;
        }
        // Load W tile 16x128 (as float4)
#pragma unroll
        for (int i = tid; i < 512; i += 256) {
            int r = i >> 5, c = i & 31;
            Bs[r][c] = *(const float4*)(W + (size_t)(k0 + r) * HDIM + c * 4);
        }
        __syncthreads();
#pragma unroll
        for (int kk = 0; kk < 16; kk++) {
            float a[8];
#pragma unroll
            for (int i = 0; i < 8; i++) a[i] = As[rg * 8 + i][kk];
            float4 b = Bs[kk][cg];
#pragma unroll
            for (int i = 0; i < 8; i++) {
                acc[i][0] += a[i] * b.x; acc[i][1] += a[i] * b.y;
                acc[i][2] += a[i] * b.z; acc[i][3] += a[i] * b.w;
            }
        }
        __syncthreads();
    }

    // Epilogue: bn + relu (+ residual), float4 stores (one full row per warp/i)
    float s[4], sh[4], bb[4];
#pragma unroll
    for (int j = 0; j < 4; j++) {
        int c = cg * 4 + j;
        s[j]  = g[c] * rsqrtf(v[c] + EPS);
        sh[j] = be[c] - m[c] * s[j];
        bb[j] = bias[c];
    }
#pragma unroll
    for (int i = 0; i < 8; i++) {
        int rr = rowBase + rg * 8 + i;
        if (rr < M) {
            float4 o;
            o.x = fmaxf((acc[i][0] + bb[0]) * s[0] + sh[0], 0.f);
            o.y = fmaxf((acc[i][1] + bb[1]) * s[1] + sh[1], 0.f);
            o.z = fmaxf((acc[i][2] + bb[2]) * s[2] + sh[2], 0.f);
            o.w = fmaxf((acc[i][3] + bb[3]) * s[3] + sh[3], 0.f);
            if (RES) {
                float4 r4 = *(const float4*)(ident + (size_t)rr * HDIM + cg * 4);
                o.x += r4.x; o.y += r4.y; o.z += r4.z; o.w += r4.w;
            }
            *(float4*)(out + (size_t)rr * HDIM + cg * 4) = o;
        }
    }
}

// ---------------------------------------------------------------------------
// Edge-norm precompute
// ---------------------------------------------------------------------------
__global__ void zero_f(float* __restrict__ p, int n) {
    int i = blockIdx.x * blockDim.x + threadIdx.x;
    if (i < n) p[i] = 0.f;
}

__global__ void wsum_kernel(const int* __restrict__ row,
                            const float* __restrict__ w,
                            float* __restrict__ ws) {
    int i = blockIdx.x * blockDim.x + threadIdx.x;
    if (i < NEDGES) atomicAdd(&ws[row[i]], w[i]);
}

__global__ void enorm_kernel(const int* __restrict__ row,
                             const float* __restrict__ w,
                             const float* __restrict__ ws,
                             float* __restrict__ en) {
    int i = blockIdx.x * blockDim.x + threadIdx.x;
    if (i < NEDGES) en[i] = 0.9f * w[i] / fmaxf(ws[row[i]], 1.0f);  // folds (1-ALPHA)
}

__global__ void softmax6(const float* __restrict__ att, float* __restrict__ sw) {
    if (threadIdx.x == 0 && blockIdx.x == 0) {
        float mx = -1e30f;
        for (int i = 0; i < KHOPS + 1; i++) mx = fmaxf(mx, att[i]);
        float e[KHOPS + 1], sum = 0.f;
        for (int i = 0; i < KHOPS + 1; i++) { e[i] = expf(att[i] - mx); sum += e[i]; }
        for (int i = 0; i < KHOPS + 1; i++) sw[i] = e[i] / sum;
    }
}

// ---------------------------------------------------------------------------
// Propagation step kernels
// dst = 0.1 * h0   (ALPHA fold)
// ---------------------------------------------------------------------------
__global__ void init_alpha(float* __restrict__ dst, const float* __restrict__ h0) {
    int i = blockIdx.x * blockDim.x + threadIdx.x;
    if (i < NNODES * HDIM / 4) {
        float4 s = ((const float4*)h0)[i];
        s.x *= 0.1f; s.y *= 0.1f; s.z *= 0.1f; s.w *= 0.1f;
        ((float4*)dst)[i] = s;
    }
}

// Warp-per-edge gather/scatter: dst[col] += en * src[row]  (128 floats = 32 x float4)
__global__ void scatter_kernel(const float* __restrict__ src,
                               float* __restrict__ dst,
                               const int* __restrict__ row,
                               const int* __restrict__ col,
                               const float* __restrict__ en) {
    int e = blockIdx.x * (blockDim.x >> 5) + (threadIdx.x >> 5);
    if (e >= NEDGES) return;
    int lane = threadIdx.x & 31;
    int r = __ldg(row + e);
    int c = __ldg(col + e);
    float w = __ldg(en + e);
    float4 v = __ldg(((const float4*)(src + (size_t)r * HDIM)) + lane);
    v.x *= w; v.y *= w; v.z *= w; v.w *= w;
    atomicAdd(((float4*)(dst + (size_t)c * HDIM)) + lane, v);
}

// F = (first ? 0 : F) + sw[k] * src
__global__ void fused_acc(float* __restrict__ F, const float* __restrict__ src,
                          const float* __restrict__ sw, int k, int first) {
    int i = blockIdx.x * blockDim.x + threadIdx.x;
    if (i < NNODES * HDIM / 4) {
        float w = __ldg(sw + k);
        float4 s = ((const float4*)src)[i];
        float4 f = first ? make_float4(0.f, 0.f, 0.f, 0.f) : ((float4*)F)[i];
        f.x += w * s.x; f.y += w * s.y; f.z += w * s.z; f.w += w * s.w;
        ((float4*)F)[i] = f;
    }
}

// ---------------------------------------------------------------------------
// Head: out = relu(bn3(F@W3 + b3)) @ W4 + b4   — one warp per node
// ---------------------------------------------------------------------------
__global__ void head_kernel(const float* __restrict__ F,
                            const float* __restrict__ W3, const float* __restrict__ b3,
                            const float* __restrict__ g3, const float* __restrict__ be3,
                            const float* __restrict__ m3, const float* __restrict__ v3,
                            const float* __restrict__ W4, const float* __restrict__ b4,
                            float* __restrict__ out) {
    __shared__ float sW3[HDIM * H2DIM];     // 32 KB
    __shared__ float sW4[H2DIM * ODIM];     // 8 KB
    __shared__ float sS3[H2DIM], sSh3[H2DIM], sB4[ODIM];
    __shared__ float fr[8][HDIM];
    __shared__ float hid[8][H2DIM];

    int tid = threadIdx.x;
    for (int i = tid; i < HDIM * H2DIM; i += blockDim.x) sW3[i] = W3[i];
    for (int i = tid; i < H2DIM * ODIM; i += blockDim.x) sW4[i] = W4[i];
    if (tid < H2DIM) {
        float s = g3[tid] * rsqrtf(v3[tid] + EPS);
        sS3[tid] = s;
        sSh3[tid] = (b3[tid] - m3[tid]) * s + be3[tid];
    }
    if (tid < ODIM) sB4[tid] = b4[tid];
    __syncthreads();

    int warp = tid >> 5, lane = tid & 31;
    int nwarps = blockDim.x >> 5;
    for (int n = blockIdx.x * nwarps + warp; n < NNODES; n += gridDim.x * nwarps) {
        ((float4*)fr[warp])[lane] = ((const float4*)(F + (size_t)n * HDIM))[lane];
        __syncwarp();
#pragma unroll
        for (int half = 0; half < 2; half++) {
            int j = lane + 32 * half;
            float acc = 0.f;
#pragma unroll 8
            for (int k = 0; k < HDIM; k++) acc += fr[warp][k] * sW3[k * H2DIM + j];
            hid[warp][j] = fmaxf(acc * sS3[j] + sSh3[j], 0.f);
        }
        __syncwarp();
        float acc = sB4[lane];
#pragma unroll 8
        for (int j = 0; j < H2DIM; j++) acc += hid[warp][j] * sW4[j * ODIM + lane];
        out[(size_t)n * ODIM + lane] = acc;
        __syncwarp();
    }
}

// ---------------------------------------------------------------------------
// Launch
// ---------------------------------------------------------------------------
extern "C" void kernel_launch(void* const* d_in, const int* in_sizes, int n_in,
                              void* d_out, int out_size) {
    const float* x   = (const float*)d_in[0];
    const int*   ei  = (const int*)d_in[1];
    const float* ew  = (const float*)d_in[2];
    const float* W1  = (const float*)d_in[3];
    const float* b1  = (const float*)d_in[4];
    const float* g1  = (const float*)d_in[5];
    const float* be1 = (const float*)d_in[6];
    const float* m1  = (const float*)d_in[7];
    const float* v1  = (const float*)d_in[8];
    const float* W2  = (const float*)d_in[9];
    const float* b2  = (const float*)d_in[10];
    const float* g2  = (const float*)d_in[11];
    const float* be2 = (const float*)d_in[12];
    const float* m2  = (const float*)d_in[13];
    const float* v2  = (const float*)d_in[14];
    const float* att = (const float*)d_in[15];
    const float* W3  = (const float*)d_in[16];
    const float* b3  = (const float*)d_in[17];
    const float* g3  = (const float*)d_in[18];
    const float* be3 = (const float*)d_in[19];
    const float* m3  = (const float*)d_in[20];
    const float* v3  = (const float*)d_in[21];
    const float* W4  = (const float*)d_in[22];
    const float* b4  = (const float*)d_in[23];

    const int* row = ei;
    const int* col = ei + NEDGES;

    float *B0, *B1, *B2, *F, *WS, *EN, *SW;
    cudaGetSymbolAddress((void**)&B0, gB0);
    cudaGetSymbolAddress((void**)&B1, gB1);
    cudaGetSymbolAddress((void**)&B2, gB2);
    cudaGetSymbolAddress((void**)&F,  gFz);
    cudaGetSymbolAddress((void**)&WS, gWsum);
    cudaGetSymbolAddress((void**)&EN, gEN);
    cudaGetSymbolAddress((void**)&SW, gSw);

    const int gemmBlocks = (NNODES + 63) / 64;
    const int elemBlocks = (NNODES * HDIM / 4 + 255) / 256;
    const int edgeBlocks = (NEDGES + 255) / 256;
    const int scatBlocks = (NEDGES + 7) / 8;

    // Feature MLP: h1 = relu(bn1(x@W1+b1)) -> B1 ; hc = relu(bn2(h1@W2+b2)) + h1 -> B0
    gemm_bn_relu<IN_DIM, false><<<gemmBlocks, 256>>>(x,  W1, b1, g1, be1, m1, v1, nullptr, B1, NNODES);
    gemm_bn_relu<HDIM,   true ><<<gemmBlocks, 256>>>(B1, W2, b2, g2, be2, m2, v2, B1,      B0, NNODES);

    // edge normalization (fold 0.9)
    zero_f<<<(NNODES + 255) / 256, 256>>>(WS, NNODES);
    wsum_kernel<<<edgeBlocks, 256>>>(row, ew, WS);
    enorm_kernel<<<edgeBlocks, 256>>>(row, ew, WS, EN);
    softmax6<<<1, 32>>>(att, SW);

    // fused = sw[0] * hc
    fused_acc<<<elemBlocks, 256>>>(F, B0, SW, 0, 1);

    // Propagation: outer K x inner K, 3 rotating buffers
    float* hc = B0;
    float* f0 = B1;
    float* f1 = B2;
    for (int k = 0; k < KHOPS; k++) {
        float* h0  = hc;
        float* src = h0;
        float* a = f0;
        float* b = f1;
        for (int t = 0; t < KHOPS; t++) {
            init_alpha<<<elemBlocks, 256>>>(a, h0);
            scatter_kernel<<<scatBlocks, 256>>>(src, a, row, col, EN);
            src = a;
            float* tmp = a; a = b; b = tmp;
        }
        hc = src;          // final hk of this outer iteration
        f0 = a;            // unused ping-pong buffer
        f1 = h0;           // old h0 is now free
        fused_acc<<<elemBlocks, 256>>>(F, hc, SW, k + 1, 0);
    }

    // Head
    head_kernel<<<1184, 256>>>(F, W3, b3, g3, be3, m3, v3, W4, b4, (float*)d_out);
}

// round 2
// speedup vs baseline: 2.2990x; 2.2990x over previous
#include <cuda_runtime.h>
#include <cuda_bf16.h>

// Problem constants
#define NNODES 50000
#define NEDGES 800000
#define IN_DIM 256
#define HDIM   128
#define H2DIM  64
#define ODIM   32
#define KHOPS  5
#define EPS    1e-5f

// ---------------------------------------------------------------------------
// Scratch (device globals; no allocation allowed)
// ---------------------------------------------------------------------------
__device__ float gB0[NNODES * HDIM];
__device__ float gB1[NNODES * HDIM];
__device__ float gB2[NNODES * HDIM];
__device__ float gFz[NNODES * HDIM];
__device__ float gWsum[NNODES];
__device__ int   gDeg[NNODES];
__device__ int   gCur[NNODES];
__device__ int   gOff[NNODES + 1];
__device__ int   gEsrc[NEDGES];
__device__ float gEwt[NEDGES];
__device__ float gSw[8];

// ---------------------------------------------------------------------------
// Tiled fp32 GEMM  out = relu(bn(A@W + b)) [+ ident]
// ---------------------------------------------------------------------------
template <int KDIM, bool RES>
__global__ void gemm_bn_relu(const float* __restrict__ A,
                             const float* __restrict__ W,
                             const float* __restrict__ bias,
                             const float* __restrict__ g,
                             const float* __restrict__ be,
                             const float* __restrict__ m,
                             const float* __restrict__ v,
                             const float* __restrict__ ident,
                             float* __restrict__ out, int M) {
    __shared__ float  As[64][17];
    __shared__ float4 Bs[16][32];
    const int tid = threadIdx.x;
    const int rowBase = blockIdx.x * 64;
    const int cg = tid & 31;
    const int rg = tid >> 5;

    float acc[8][4];
#pragma unroll
    for (int i = 0; i < 8; i++)
#pragma unroll
        for (int j = 0; j < 4; j++) acc[i][j] = 0.f;

    for (int k0 = 0; k0 < KDIM; k0 += 16) {
        {
            int r = tid >> 2, c4 = tid & 3;
            float4 val = make_float4(0.f, 0.f, 0.f, 0.f);
            if (rowBase + r < M)
                val = *(const float4*)(A + (size_t)(rowBase + r) * KDIM + k0 + c4 * 4);
            As[r][c4 * 4 + 0] = val.x; As[r][c4 * 4 + 1] = val.y;
            As[r][c4 * 4 + 2] = val.z; As[r][c4 * 4 + 3] = val.w;
        }
#pragma unroll
        for (int i = tid; i < 512; i += 256) {
            int r = i >> 5, c = i & 31;
            Bs[r][c] = *(const float4*)(W + (size_t)(k0 + r) * HDIM + c * 4);
        }
        __syncthreads();
#pragma unroll
        for (int kk = 0; kk < 16; kk++) {
            float a[8];
#pragma unroll
            for (int i = 0; i < 8; i++) a[i] = As[rg * 8 + i][kk];
            float4 b = Bs[kk][cg];
#pragma unroll
            for (int i = 0; i < 8; i++) {
                acc[i][0] += a[i] * b.x; acc[i][1] += a[i] * b.y;
                acc[i][2] += a[i] * b.z; acc[i][3] += a[i] * b.w;
            }
        }
        __syncthreads();
    }

    float s[4], sh[4], bb[4];
#pragma unroll
    for (int j = 0; j < 4; j++) {
        int c = cg * 4 + j;
        s[j]  = g[c] * rsqrtf(v[c] + EPS);
        sh[j] = be[c] - m[c] * s[j];
        bb[j] = bias[c];
    }
#pragma unroll
    for (int i = 0; i < 8; i++) {
        int rr = rowBase + rg * 8 + i;
        if (rr < M) {
            float4 o;
            o.x = fmaxf((acc[i][0] + bb[0]) * s[0] + sh[0], 0.f);
            o.y = fmaxf((acc[i][1] + bb[1]) * s[1] + sh[1], 0.f);
            o.z = fmaxf((acc[i][2] + bb[2]) * s[2] + sh[2], 0.f);
            o.w = fmaxf((acc[i][3] + bb[3]) * s[3] + sh[3], 0.f);
            if (RES) {
                float4 r4 = *(const float4*)(ident + (size_t)rr * HDIM + cg * 4);
                o.x += r4.x; o.y += r4.y; o.z += r4.z; o.w += r4.w;
            }
            *(float4*)(out + (size_t)rr * HDIM + cg * 4) = o;
        }
    }
}

// ---------------------------------------------------------------------------
// CSC build
// ---------------------------------------------------------------------------
__global__ void zero_ws_deg(float* __restrict__ ws, int* __restrict__ deg) {
    int i = blockIdx.x * blockDim.x + threadIdx.x;
    if (i < NNODES) { ws[i] = 0.f; deg[i] = 0; }
}

// ws[row[e]] += w[e];  deg[col[e]] += 1
__global__ void wsum_deg_kernel(const int* __restrict__ row,
                                const int* __restrict__ col,
                                const float* __restrict__ w,
                                float* __restrict__ ws,
                                int* __restrict__ deg) {
    int i = blockIdx.x * blockDim.x + threadIdx.x;
    if (i < NEDGES) {
        atomicAdd(&ws[row[i]], w[i]);
        atomicAdd(&deg[col[i]], 1);
    }
}

// Single-block exclusive scan over 50000 degrees -> off[0..N], cursor copy
__global__ void scan_offsets(const int* __restrict__ deg,
                             int* __restrict__ off,
                             int* __restrict__ cursor) {
    __shared__ int partial[1024];
    const int CH = (NNODES + 1023) / 1024;   // 49
    int tid = threadIdx.x;
    int start = tid * CH;
    int sum = 0;
    for (int j = 0; j < CH; j++) {
        int idx = start + j;
        if (idx < NNODES) sum += deg[idx];
    }
    partial[tid] = sum;
    __syncthreads();
    for (int d = 1; d < 1024; d <<= 1) {
        int t = (tid >= d) ? partial[tid - d] : 0;
        __syncthreads();
        partial[tid] += t;
        __syncthreads();
    }
    int run = (tid == 0) ? 0 : partial[tid - 1];
    for (int j = 0; j < CH; j++) {
        int idx = start + j;
        if (idx < NNODES) {
            off[idx] = run;
            cursor[idx] = run;
            run += deg[idx];
        }
    }
    if (tid == 1023) off[NNODES] = NEDGES;
}

// Fill CSC: esrc[pos]=row, ewt[pos]=0.9*w/max(ws[row],1)
__global__ void fill_csc(const int* __restrict__ row,
                         const int* __restrict__ col,
                         const float* __restrict__ w,
                         const float* __restrict__ ws,
                         int* __restrict__ cursor,
                         int* __restrict__ esrc,
                         float* __restrict__ ewt) {
    int i = blockIdx.x * blockDim.x + threadIdx.x;
    if (i < NEDGES) {
        int r = row[i];
        int c = col[i];
        int pos = atomicAdd(&cursor[c], 1);
        esrc[pos] = r;
        ewt[pos] = 0.9f * w[i] / fmaxf(ws[r], 1.0f);
    }
}

__global__ void softmax6(const float* __restrict__ att, float* __restrict__ sw) {
    if (threadIdx.x == 0 && blockIdx.x == 0) {
        float mx = -1e30f;
        for (int i = 0; i < KHOPS + 1; i++) mx = fmaxf(mx, att[i]);
        float e[KHOPS + 1], sum = 0.f;
        for (int i = 0; i < KHOPS + 1; i++) { e[i] = expf(att[i] - mx); sum += e[i]; }
        for (int i = 0; i < KHOPS + 1; i++) sw[i] = e[i] / sum;
    }
}

// F = sw[0] * src
__global__ void fused_init(float* __restrict__ F, const float* __restrict__ src,
                           const float* __restrict__ sw) {
    int i = blockIdx.x * blockDim.x + threadIdx.x;
    if (i < NNODES * HDIM / 4) {
        float w = __ldg(sw);
        float4 s = ((const float4*)src)[i];
        s.x *= w; s.y *= w; s.z *= w; s.w *= w;
        ((float4*)F)[i] = s;
    }
}

// ---------------------------------------------------------------------------
// Propagation gather step (warp per destination node, no atomics):
//   dst[n] = 0.1*h0[n] + sum_{e in in(n)} ewt[e] * src[esrc[e]]
// If ACCF: F[n] += sw[swIdx] * dst[n]
// ---------------------------------------------------------------------------
template <bool ACCF>
__global__ void prop_gather(const float* __restrict__ src,
                            const float* __restrict__ h0,
                            float* __restrict__ dst,
                            const int* __restrict__ off,
                            const int* __restrict__ esrc,
                            const float* __restrict__ ewt,
                            float* __restrict__ F,
                            const float* __restrict__ sw, int swIdx) {
    int warp = (blockIdx.x * blockDim.x + threadIdx.x) >> 5;
    if (warp >= NNODES) return;
    int lane = threadIdx.x & 31;

    int s = __ldg(off + warp);
    int e = __ldg(off + warp + 1);

    float4 h = __ldg(((const float4*)(h0 + (size_t)warp * HDIM)) + lane);
    float4 acc0 = make_float4(0.1f * h.x, 0.1f * h.y, 0.1f * h.z, 0.1f * h.w);
    float4 acc1 = make_float4(0.f, 0.f, 0.f, 0.f);

    int i = s;
    for (; i + 1 < e; i += 2) {
        int   s0 = __ldg(esrc + i);
        int   s1 = __ldg(esrc + i + 1);
        float w0 = __ldg(ewt + i);
        float w1 = __ldg(ewt + i + 1);
        float4 v0 = __ldg(((const float4*)(src + (size_t)s0 * HDIM)) + lane);
        float4 v1 = __ldg(((const float4*)(src + (size_t)s1 * HDIM)) + lane);
        acc0.x += w0 * v0.x; acc0.y += w0 * v0.y; acc0.z += w0 * v0.z; acc0.w += w0 * v0.w;
        acc1.x += w1 * v1.x; acc1.y += w1 * v1.y; acc1.z += w1 * v1.z; acc1.w += w1 * v1.w;
    }
    if (i < e) {
        int   s0 = __ldg(esrc + i);
        float w0 = __ldg(ewt + i);
        float4 v0 = __ldg(((const float4*)(src + (size_t)s0 * HDIM)) + lane);
        acc0.x += w0 * v0.x; acc0.y += w0 * v0.y; acc0.z += w0 * v0.z; acc0.w += w0 * v0.w;
    }
    acc0.x += acc1.x; acc0.y += acc1.y; acc0.z += acc1.z; acc0.w += acc1.w;

    *(((float4*)(dst + (size_t)warp * HDIM)) + lane) = acc0;

    if (ACCF) {
        float fw = __ldg(sw + swIdx);
        float4* fp = ((float4*)(F + (size_t)warp * HDIM)) + lane;
        float4 f = *fp;
        f.x += fw * acc0.x; f.y += fw * acc0.y; f.z += fw * acc0.z; f.w += fw * acc0.w;
        *fp = f;
    }
}

// ---------------------------------------------------------------------------
// Head: out = relu(bn3(F@W3 + b3)) @ W4 + b4   — one warp per node
// ---------------------------------------------------------------------------
__global__ void head_kernel(const float* __restrict__ F,
                            const float* __restrict__ W3, const float* __restrict__ b3,
                            const float* __restrict__ g3, const float* __restrict__ be3,
                            const float* __restrict__ m3, const float* __restrict__ v3,
                            const float* __restrict__ W4, const float* __restrict__ b4,
                            float* __restrict__ out) {
    __shared__ float sW3[HDIM * H2DIM];
    __shared__ float sW4[H2DIM * ODIM];
    __shared__ float sS3[H2DIM], sSh3[H2DIM], sB4[ODIM];
    __shared__ float fr[8][HDIM];
    __shared__ float hid[8][H2DIM];

    int tid = threadIdx.x;
    for (int i = tid; i < HDIM * H2DIM; i += blockDim.x) sW3[i] = W3[i];
    for (int i = tid; i < H2DIM * ODIM; i += blockDim.x) sW4[i] = W4[i];
    if (tid < H2DIM) {
        float s = g3[tid] * rsqrtf(v3[tid] + EPS);
        sS3[tid] = s;
        sSh3[tid] = (b3[tid] - m3[tid]) * s + be3[tid];
    }
    if (tid < ODIM) sB4[tid] = b4[tid];
    __syncthreads();

    int warp = tid >> 5, lane = tid & 31;
    int nwarps = blockDim.x >> 5;
    for (int n = blockIdx.x * nwarps + warp; n < NNODES; n += gridDim.x * nwarps) {
        ((float4*)fr[warp])[lane] = ((const float4*)(F + (size_t)n * HDIM))[lane];
        __syncwarp();
#pragma unroll
        for (int half = 0; half < 2; half++) {
            int j = lane + 32 * half;
            float acc = 0.f;
#pragma unroll 8
            for (int k = 0; k < HDIM; k++) acc += fr[warp][k] * sW3[k * H2DIM + j];
            hid[warp][j] = fmaxf(acc * sS3[j] + sSh3[j], 0.f);
        }
        __syncwarp();
        float acc = sB4[lane];
#pragma unroll 8
        for (int j = 0; j < H2DIM; j++) acc += hid[warp][j] * sW4[j * ODIM + lane];
        out[(size_t)n * ODIM + lane] = acc;
        __syncwarp();
    }
}

// ---------------------------------------------------------------------------
// Launch
// ---------------------------------------------------------------------------
extern "C" void kernel_launch(void* const* d_in, const int* in_sizes, int n_in,
                              void* d_out, int out_size) {
    const float* x   = (const float*)d_in[0];
    const int*   ei  = (const int*)d_in[1];
    const float* ew  = (const float*)d_in[2];
    const float* W1  = (const float*)d_in[3];
    const float* b1  = (const float*)d_in[4];
    const float* g1  = (const float*)d_in[5];
    const float* be1 = (const float*)d_in[6];
    const float* m1  = (const float*)d_in[7];
    const float* v1  = (const float*)d_in[8];
    const float* W2  = (const float*)d_in[9];
    const float* b2  = (const float*)d_in[10];
    const float* g2  = (const float*)d_in[11];
    const float* be2 = (const float*)d_in[12];
    const float* m2  = (const float*)d_in[13];
    const float* v2  = (const float*)d_in[14];
    const float* att = (const float*)d_in[15];
    const float* W3  = (const float*)d_in[16];
    const float* b3  = (const float*)d_in[17];
    const float* g3  = (const float*)d_in[18];
    const float* be3 = (const float*)d_in[19];
    const float* m3  = (const float*)d_in[20];
    const float* v3  = (const float*)d_in[21];
    const float* W4  = (const float*)d_in[22];
    const float* b4  = (const float*)d_in[23];

    const int* row = ei;
    const int* col = ei + NEDGES;

    float *B0, *B1, *B2, *F, *WS, *EWT, *SW;
    int *DEG, *CUR, *OFF, *ESRC;
    cudaGetSymbolAddress((void**)&B0,   gB0);
    cudaGetSymbolAddress((void**)&B1,   gB1);
    cudaGetSymbolAddress((void**)&B2,   gB2);
    cudaGetSymbolAddress((void**)&F,    gFz);
    cudaGetSymbolAddress((void**)&WS,   gWsum);
    cudaGetSymbolAddress((void**)&DEG,  gDeg);
    cudaGetSymbolAddress((void**)&CUR,  gCur);
    cudaGetSymbolAddress((void**)&OFF,  gOff);
    cudaGetSymbolAddress((void**)&ESRC, gEsrc);
    cudaGetSymbolAddress((void**)&EWT,  gEwt);
    cudaGetSymbolAddress((void**)&SW,   gSw);

    const int gemmBlocks = (NNODES + 63) / 64;
    const int elemBlocks = (NNODES * HDIM / 4 + 255) / 256;
    const int edgeBlocks = (NEDGES + 255) / 256;
    const int propBlocks = (NNODES * 32 + 255) / 256;   // warp per node, 8 warps/block

    // Feature MLP
    gemm_bn_relu<IN_DIM, false><<<gemmBlocks, 256>>>(x,  W1, b1, g1, be1, m1, v1, nullptr, B1, NNODES);
    gemm_bn_relu<HDIM,   true ><<<gemmBlocks, 256>>>(B1, W2, b2, g2, be2, m2, v2, B1,      B0, NNODES);

    // CSC build
    zero_ws_deg<<<(NNODES + 255) / 256, 256>>>(WS, DEG);
    wsum_deg_kernel<<<edgeBlocks, 256>>>(row, col, ew, WS, DEG);
    scan_offsets<<<1, 1024>>>(DEG, OFF, CUR);
    fill_csc<<<edgeBlocks, 256>>>(row, col, ew, WS, CUR, ESRC, EWT);
    softmax6<<<1, 32>>>(att, SW);

    // fused = sw[0] * hc
    fused_init<<<elemBlocks, 256>>>(F, B0, SW);

    // Propagation: K outer x K inner, 3 rotating buffers, gather-based
    float* hc = B0;
    float* f0 = B1;
    float* f1 = B2;
    for (int k = 0; k < KHOPS; k++) {
        float* h0  = hc;
        float* src = h0;
        float* a = f0;
        float* b = f1;
        for (int t = 0; t < KHOPS; t++) {
            if (t == KHOPS - 1)
                prop_gather<true ><<<propBlocks, 256>>>(src, h0, a, OFF, ESRC, EWT, F, SW, k + 1);
            else
                prop_gather<false><<<propBlocks, 256>>>(src, h0, a, OFF, ESRC, EWT, nullptr, SW, 0);
            src = a;
            float* tmp = a; a = b; b = tmp;
        }
        hc = src;
        f0 = a;
        f1 = h0;
    }

    // Head
    head_kernel<<<1184, 256>>>(F, W3, b3, g3, be3, m3, v3, W4, b4, (float*)d_out);
}

// round 3
// speedup vs baseline: 2.3828x; 1.0364x over previous
#include <cuda_runtime.h>
#include <cuda_fp16.h>
#include <cuda_bf16.h>

// Problem constants
#define NNODES 50000
#define NEDGES 800000
#define IN_DIM 256
#define HDIM   128
#define H2DIM  64
#define ODIM   32
#define KHOPS  5
#define EPS    1e-5f

// ---------------------------------------------------------------------------
// Scratch (device globals; no allocation allowed)
// ---------------------------------------------------------------------------
__device__ float  gB0[NNODES * HDIM];      // fp32 state A
__device__ float  gB1[NNODES * HDIM];      // fp32 state B
__device__ float  gFz[NNODES * HDIM];      // fused accumulator
__device__ __half gHa[NNODES * HDIM];      // fp16 state ping
__device__ __half gHb[NNODES * HDIM];      // fp16 state pong
__device__ float  gWsum[NNODES];
__device__ int    gDeg[NNODES];
__device__ int    gCur[NNODES];
__device__ int    gOff[NNODES + 1];
__device__ int2   gEdge[NEDGES];           // {src, __float_as_int(weight)}
__device__ float  gSw[8];

// ---------------------------------------------------------------------------
// Tiled fp32 GEMM  out = relu(bn(A@W + b)) [+ ident]
// If FUSEP: also write fp16 copy to out16 and F = sw[0]*out
// ---------------------------------------------------------------------------
template <int KDIM, bool RES, bool FUSEP>
__global__ void gemm_bn_relu(const float* __restrict__ A,
                             const float* __restrict__ W,
                             const float* __restrict__ bias,
                             const float* __restrict__ g,
                             const float* __restrict__ be,
                             const float* __restrict__ m,
                             const float* __restrict__ v,
                             const float* __restrict__ ident,
                             float* __restrict__ out,
                             __half* __restrict__ out16,
                             float* __restrict__ F,
                             const float* __restrict__ sw, int M) {
    __shared__ float  As[64][17];
    __shared__ float4 Bs[16][32];
    const int tid = threadIdx.x;
    const int rowBase = blockIdx.x * 64;
    const int cg = tid & 31;
    const int rg = tid >> 5;

    float acc[8][4];
#pragma unroll
    for (int i = 0; i < 8; i++)
#pragma unroll
        for (int j = 0; j < 4; j++) acc[i][j] = 0.f;

    for (int k0 = 0; k0 < KDIM; k0 += 16) {
        {
            int r = tid >> 2, c4 = tid & 3;
            float4 val = make_float4(0.f, 0.f, 0.f, 0.f);
            if (rowBase + r < M)
                val = *(const float4*)(A + (size_t)(rowBase + r) * KDIM + k0 + c4 * 4);
            As[r][c4 * 4 + 0] = val.x; As[r][c4 * 4 + 1] = val.y;
            As[r][c4 * 4 + 2] = val.z; As[r][c4 * 4 + 3] = val.w;
        }
#pragma unroll
        for (int i = tid; i < 512; i += 256) {
            int r = i >> 5, c = i & 31;
            Bs[r][c] = *(const float4*)(W + (size_t)(k0 + r) * HDIM + c * 4);
        }
        __syncthreads();
#pragma unroll
        for (int kk = 0; kk < 16; kk++) {
            float a[8];
#pragma unroll
            for (int i = 0; i < 8; i++) a[i] = As[rg * 8 + i][kk];
            float4 b = Bs[kk][cg];
#pragma unroll
            for (int i = 0; i < 8; i++) {
                acc[i][0] += a[i] * b.x; acc[i][1] += a[i] * b.y;
                acc[i][2] += a[i] * b.z; acc[i][3] += a[i] * b.w;
            }
        }
        __syncthreads();
    }

    float s[4], sh[4], bb[4];
#pragma unroll
    for (int j = 0; j < 4; j++) {
        int c = cg * 4 + j;
        s[j]  = g[c] * rsqrtf(v[c] + EPS);
        sh[j] = be[c] - m[c] * s[j];
        bb[j] = bias[c];
    }
    float fw = FUSEP ? __ldg(sw) : 0.f;
#pragma unroll
    for (int i = 0; i < 8; i++) {
        int rr = rowBase + rg * 8 + i;
        if (rr < M) {
            float4 o;
            o.x = fmaxf((acc[i][0] + bb[0]) * s[0] + sh[0], 0.f);
            o.y = fmaxf((acc[i][1] + bb[1]) * s[1] + sh[1], 0.f);
            o.z = fmaxf((acc[i][2] + bb[2]) * s[2] + sh[2], 0.f);
            o.w = fmaxf((acc[i][3] + bb[3]) * s[3] + sh[3], 0.f);
            if (RES) {
                float4 r4 = *(const float4*)(ident + (size_t)rr * HDIM + cg * 4);
                o.x += r4.x; o.y += r4.y; o.z += r4.z; o.w += r4.w;
            }
            *(float4*)(out + (size_t)rr * HDIM + cg * 4) = o;
            if (FUSEP) {
                __half2 h0 = __floats2half2_rn(o.x, o.y);
                __half2 h1 = __floats2half2_rn(o.z, o.w);
                uint2 hv = make_uint2(*(unsigned*)&h0, *(unsigned*)&h1);
                ((uint2*)(out16 + (size_t)rr * HDIM))[cg] = hv;
                float4 f = make_float4(fw * o.x, fw * o.y, fw * o.z, fw * o.w);
                *(float4*)(F + (size_t)rr * HDIM + cg * 4) = f;
            }
        }
    }
}

// ---------------------------------------------------------------------------
// CSC build
// ---------------------------------------------------------------------------
__global__ void zero_ws_deg(float* __restrict__ ws, int* __restrict__ deg) {
    int i = blockIdx.x * blockDim.x + threadIdx.x;
    if (i < NNODES) { ws[i] = 0.f; deg[i] = 0; }
}

__global__ void wsum_deg_kernel(const int* __restrict__ row,
                                const int* __restrict__ col,
                                const float* __restrict__ w,
                                float* __restrict__ ws,
                                int* __restrict__ deg) {
    int i = blockIdx.x * blockDim.x + threadIdx.x;
    if (i < NEDGES) {
        atomicAdd(&ws[row[i]], w[i]);
        atomicAdd(&deg[col[i]], 1);
    }
}

__global__ void scan_offsets(const int* __restrict__ deg,
                             int* __restrict__ off,
                             int* __restrict__ cursor) {
    __shared__ int partial[1024];
    const int CH = (NNODES + 1023) / 1024;
    int tid = threadIdx.x;
    int start = tid * CH;
    int sum = 0;
    for (int j = 0; j < CH; j++) {
        int idx = start + j;
        if (idx < NNODES) sum += deg[idx];
    }
    partial[tid] = sum;
    __syncthreads();
    for (int d = 1; d < 1024; d <<= 1) {
        int t = (tid >= d) ? partial[tid - d] : 0;
        __syncthreads();
        partial[tid] += t;
        __syncthreads();
    }
    int run = (tid == 0) ? 0 : partial[tid - 1];
    for (int j = 0; j < CH; j++) {
        int idx = start + j;
        if (idx < NNODES) {
            off[idx] = run;
            cursor[idx] = run;
            run += deg[idx];
        }
    }
    if (tid == 1023) off[NNODES] = NEDGES;
}

__global__ void fill_csc(const int* __restrict__ row,
                         const int* __restrict__ col,
                         const float* __restrict__ w,
                         const float* __restrict__ ws,
                         int* __restrict__ cursor,
                         int2* __restrict__ edge) {
    int i = blockIdx.x * blockDim.x + threadIdx.x;
    if (i < NEDGES) {
        int r = row[i];
        int c = col[i];
        float wn = 0.9f * w[i] / fmaxf(ws[r], 1.0f);
        int pos = atomicAdd(&cursor[c], 1);
        edge[pos] = make_int2(r, __float_as_int(wn));
    }
}

__global__ void softmax6(const float* __restrict__ att, float* __restrict__ sw) {
    if (threadIdx.x == 0 && blockIdx.x == 0) {
        float mx = -1e30f;
        for (int i = 0; i < KHOPS + 1; i++) mx = fmaxf(mx, att[i]);
        float e[KHOPS + 1], sum = 0.f;
        for (int i = 0; i < KHOPS + 1; i++) { e[i] = expf(att[i] - mx); sum += e[i]; }
        for (int i = 0; i < KHOPS + 1; i++) sw[i] = e[i] / sum;
    }
}

// ---------------------------------------------------------------------------
// Propagation gather step (warp per destination node, fp16 messages):
//   acc = 0.1*h0[n] + sum_e w_e * src16[esrc_e]     (fp32 accumulate)
//   dst16[n] = fp16(acc)
//   if FIN: dst32[n] = acc;  F[n] += sw[swIdx]*acc
// ---------------------------------------------------------------------------
template <bool FIN>
__global__ void prop_gather_h(const __half* __restrict__ src16,
                              const float* __restrict__ h0,
                              __half* __restrict__ dst16,
                              float* __restrict__ dst32,
                              const int* __restrict__ off,
                              const int2* __restrict__ edge,
                              float* __restrict__ F,
                              const float* __restrict__ sw, int swIdx) {
    int warp = (blockIdx.x * blockDim.x + threadIdx.x) >> 5;
    if (warp >= NNODES) return;
    int lane = threadIdx.x & 31;

    int s = __ldg(off + warp);
    int e = __ldg(off + warp + 1);

    float4 h = __ldg(((const float4*)h0) + warp * 32 + lane);
    float4 a0 = make_float4(0.1f * h.x, 0.1f * h.y, 0.1f * h.z, 0.1f * h.w);
    float4 a1 = make_float4(0.f, 0.f, 0.f, 0.f);

    int i = s;
    for (; i + 1 < e; i += 2) {
        int2 e0 = __ldg(edge + i);
        int2 e1 = __ldg(edge + i + 1);
        float w0 = __int_as_float(e0.y);
        float w1 = __int_as_float(e1.y);
        uint2 p0 = __ldg(((const uint2*)(src16 + (size_t)e0.x * HDIM)) + lane);
        uint2 p1 = __ldg(((const uint2*)(src16 + (size_t)e1.x * HDIM)) + lane);
        float2 f0a = __half22float2(*(__half2*)&p0.x);
        float2 f0b = __half22float2(*(__half2*)&p0.y);
        float2 f1a = __half22float2(*(__half2*)&p1.x);
        float2 f1b = __half22float2(*(__half2*)&p1.y);
        a0.x += w0 * f0a.x; a0.y += w0 * f0a.y; a0.z += w0 * f0b.x; a0.w += w0 * f0b.y;
        a1.x += w1 * f1a.x; a1.y += w1 * f1a.y; a1.z += w1 * f1b.x; a1.w += w1 * f1b.y;
    }
    if (i < e) {
        int2 e0 = __ldg(edge + i);
        float w0 = __int_as_float(e0.y);
        uint2 p0 = __ldg(((const uint2*)(src16 + (size_t)e0.x * HDIM)) + lane);
        float2 f0a = __half22float2(*(__half2*)&p0.x);
        float2 f0b = __half22float2(*(__half2*)&p0.y);
        a0.x += w0 * f0a.x; a0.y += w0 * f0a.y; a0.z += w0 * f0b.x; a0.w += w0 * f0b.y;
    }
    a0.x += a1.x; a0.y += a1.y; a0.z += a1.z; a0.w += a1.w;

    __half2 o0 = __floats2half2_rn(a0.x, a0.y);
    __half2 o1 = __floats2half2_rn(a0.z, a0.w);
    ((uint2*)dst16)[warp * 32 + lane] = make_uint2(*(unsigned*)&o0, *(unsigned*)&o1);

    if (FIN) {
        ((float4*)dst32)[warp * 32 + lane] = a0;
        float fw = __ldg(sw + swIdx);
        float4* fp = ((float4*)F) + warp * 32 + lane;
        float4 f = *fp;
        f.x += fw * a0.x; f.y += fw * a0.y; f.z += fw * a0.z; f.w += fw * a0.w;
        *fp = f;
    }
}

// ---------------------------------------------------------------------------
// Head: out = relu(bn3(F@W3 + b3)) @ W4 + b4   — one warp per node
// ---------------------------------------------------------------------------
__global__ void head_kernel(const float* __restrict__ F,
                            const float* __restrict__ W3, const float* __restrict__ b3,
                            const float* __restrict__ g3, const float* __restrict__ be3,
                            const float* __restrict__ m3, const float* __restrict__ v3,
                            const float* __restrict__ W4, const float* __restrict__ b4,
                            float* __restrict__ out) {
    __shared__ float sW3[HDIM * H2DIM];
    __shared__ float sW4[H2DIM * ODIM];
    __shared__ float sS3[H2DIM], sSh3[H2DIM], sB4[ODIM];
    __shared__ float fr[8][HDIM];
    __shared__ float hid[8][H2DIM];

    int tid = threadIdx.x;
    for (int i = tid; i < HDIM * H2DIM; i += blockDim.x) sW3[i] = W3[i];
    for (int i = tid; i < H2DIM * ODIM; i += blockDim.x) sW4[i] = W4[i];
    if (tid < H2DIM) {
        float s = g3[tid] * rsqrtf(v3[tid] + EPS);
        sS3[tid] = s;
        sSh3[tid] = (b3[tid] - m3[tid]) * s + be3[tid];
    }
    if (tid < ODIM) sB4[tid] = b4[tid];
    __syncthreads();

    int warp = tid >> 5, lane = tid & 31;
    int nwarps = blockDim.x >> 5;
    for (int n = blockIdx.x * nwarps + warp; n < NNODES; n += gridDim.x * nwarps) {
        ((float4*)fr[warp])[lane] = ((const float4*)(F + (size_t)n * HDIM))[lane];
        __syncwarp();
#pragma unroll
        for (int half = 0; half < 2; half++) {
            int j = lane + 32 * half;
            float acc = 0.f;
#pragma unroll 8
            for (int k = 0; k < HDIM; k++) acc += fr[warp][k] * sW3[k * H2DIM + j];
            hid[warp][j] = fmaxf(acc * sS3[j] + sSh3[j], 0.f);
        }
        __syncwarp();
        float acc = sB4[lane];
#pragma unroll 8
        for (int j = 0; j < H2DIM; j++) acc += hid[warp][j] * sW4[j * ODIM + lane];
        out[(size_t)n * ODIM + lane] = acc;
        __syncwarp();
    }
}

// ---------------------------------------------------------------------------
// Launch
// ---------------------------------------------------------------------------
extern "C" void kernel_launch(void* const* d_in, const int* in_sizes, int n_in,
                              void* d_out, int out_size) {
    const float* x   = (const float*)d_in[0];
    const int*   ei  = (const int*)d_in[1];
    const float* ew  = (const float*)d_in[2];
    const float* W1  = (const float*)d_in[3];
    const float* b1  = (const float*)d_in[4];
    const float* g1  = (const float*)d_in[5];
    const float* be1 = (const float*)d_in[6];
    const float* m1  = (const float*)d_in[7];
    const float* v1  = (const float*)d_in[8];
    const float* W2  = (const float*)d_in[9];
    const float* b2  = (const float*)d_in[10];
    const float* g2  = (const float*)d_in[11];
    const float* be2 = (const float*)d_in[12];
    const float* m2  = (const float*)d_in[13];
    const float* v2  = (const float*)d_in[14];
    const float* att = (const float*)d_in[15];
    const float* W3  = (const float*)d_in[16];
    const float* b3  = (const float*)d_in[17];
    const float* g3  = (const float*)d_in[18];
    const float* be3 = (const float*)d_in[19];
    const float* m3  = (const float*)d_in[20];
    const float* v3  = (const float*)d_in[21];
    const float* W4  = (const float*)d_in[22];
    const float* b4  = (const float*)d_in[23];

    const int* row = ei;
    const int* col = ei + NEDGES;

    float *B0, *B1, *F, *WS, *SW;
    __half *HA, *HB;
    int *DEG, *CUR, *OFF;
    int2 *EDGE;
    cudaGetSymbolAddress((void**)&B0,   gB0);
    cudaGetSymbolAddress((void**)&B1,   gB1);
    cudaGetSymbolAddress((void**)&F,    gFz);
    cudaGetSymbolAddress((void**)&HA,   gHa);
    cudaGetSymbolAddress((void**)&HB,   gHb);
    cudaGetSymbolAddress((void**)&WS,   gWsum);
    cudaGetSymbolAddress((void**)&DEG,  gDeg);
    cudaGetSymbolAddress((void**)&CUR,  gCur);
    cudaGetSymbolAddress((void**)&OFF,  gOff);
    cudaGetSymbolAddress((void**)&EDGE, gEdge);
    cudaGetSymbolAddress((void**)&SW,   gSw);

    const int gemmBlocks = (NNODES + 63) / 64;
    const int edgeBlocks = (NEDGES + 255) / 256;
    const int propBlocks = (NNODES * 32 + 255) / 256;

    // Feature MLP. GEMM2 also emits fp16 state + F = sw[0]*hc.
    softmax6<<<1, 32>>>(att, SW);
    gemm_bn_relu<IN_DIM, false, false><<<gemmBlocks, 256>>>(
        x,  W1, b1, g1, be1, m1, v1, nullptr, B1, nullptr, nullptr, nullptr, NNODES);
    gemm_bn_relu<HDIM,   true,  true ><<<gemmBlocks, 256>>>(
        B1, W2, b2, g2, be2, m2, v2, B1,      B0, HA, F, SW, NNODES);

    // CSC build
    zero_ws_deg<<<(NNODES + 255) / 256, 256>>>(WS, DEG);
    wsum_deg_kernel<<<edgeBlocks, 256>>>(row, col, ew, WS, DEG);
    scan_offsets<<<1, 1024>>>(DEG, OFF, CUR);
    fill_csc<<<edgeBlocks, 256>>>(row, col, ew, WS, CUR, EDGE);

    // Propagation: K outer x K inner
    float* h32 = B0;      // fp32 hc (h0 of this outer)
    float* o32 = B1;      // fp32 output buffer for this outer
    __half* s16 = HA;     // fp16 current state
    __half* d16 = HB;
    for (int k = 0; k < KHOPS; k++) {
        for (int t = 0; t < KHOPS; t++) {
            if (t == KHOPS - 1)
                prop_gather_h<true ><<<propBlocks, 256>>>(s16, h32, d16, o32, OFF, EDGE, F, SW, k + 1);
            else
                prop_gather_h<false><<<propBlocks, 256>>>(s16, h32, d16, nullptr, OFF, EDGE, nullptr, SW, 0);
            __half* tmp = s16; s16 = d16; d16 = tmp;
        }
        float* t32 = h32; h32 = o32; o32 = t32;   // new hc is o32; old h0 becomes scratch
    }

    // Head
    head_kernel<<<1184, 256>>>(F, W3, b3, g3, be3, m3, v3, W4, b4, (float*)d_out);
}

// round 5
// speedup vs baseline: 2.5338x; 1.0634x over previous
#include <cuda_runtime.h>
#include <cuda_fp16.h>
#include <cuda_bf16.h>

// Problem constants
#define NNODES 50000
#define NEDGES 800000
#define IN_DIM 256
#define HDIM   128
#define H2DIM  64
#define ODIM   32
#define KHOPS  5
#define EPS    1e-5f

// ---------------------------------------------------------------------------
// Scratch (device globals; no allocation allowed)
// ---------------------------------------------------------------------------
__device__ float  gB1[NNODES * HDIM];      // GEMM1 output
__device__ float  gFz[NNODES * HDIM];      // fused accumulator
__device__ __half gH0[NNODES * HDIM];      // fp16 state buffers (rotating)
__device__ __half gH1[NNODES * HDIM];
__device__ __half gH2[NNODES * HDIM];
__device__ float  gWsum[NNODES];
__device__ int    gDeg[NNODES];
__device__ int    gCur[NNODES];
__device__ int    gOff[NNODES + 1];
__device__ int2   gEdge[NEDGES];           // {src, __float_as_int(weight)}
__device__ float  gSw[8];

// ---------------------------------------------------------------------------
// Tiled fp32 GEMM.
// FUSEP=false: out32 = relu(bn(A@W+b))            (writes fp32)
// FUSEP=true : t = relu(bn(A@W+b)) + ident; out16 = fp16(t); F = sw[0]*t
// ---------------------------------------------------------------------------
template <int KDIM, bool RES, bool FUSEP>
__global__ void gemm_bn_relu(const float* __restrict__ A,
                             const float* __restrict__ W,
                             const float* __restrict__ bias,
                             const float* __restrict__ g,
                             const float* __restrict__ be,
                             const float* __restrict__ m,
                             const float* __restrict__ v,
                             const float* __restrict__ ident,
                             float* __restrict__ out32,
                             __half* __restrict__ out16,
                             float* __restrict__ F,
                             const float* __restrict__ sw, int M) {
    __shared__ float  As[64][17];
    __shared__ float4 Bs[16][32];
    const int tid = threadIdx.x;
    const int rowBase = blockIdx.x * 64;
    const int cg = tid & 31;
    const int rg = tid >> 5;

    float acc[8][4];
#pragma unroll
    for (int i = 0; i < 8; i++)
#pragma unroll
        for (int j = 0; j < 4; j++) acc[i][j] = 0.f;

    for (int k0 = 0; k0 < KDIM; k0 += 16) {
        {
            int r = tid >> 2, c4 = tid & 3;
            float4 val = make_float4(0.f, 0.f, 0.f, 0.f);
            if (rowBase + r < M)
                val = *(const float4*)(A + (size_t)(rowBase + r) * KDIM + k0 + c4 * 4);
            As[r][c4 * 4 + 0] = val.x; As[r][c4 * 4 + 1] = val.y;
            As[r][c4 * 4 + 2] = val.z; As[r][c4 * 4 + 3] = val.w;
        }
#pragma unroll
        for (int i = tid; i < 512; i += 256) {
            int r = i >> 5, c = i & 31;
            Bs[r][c] = *(const float4*)(W + (size_t)(k0 + r) * HDIM + c * 4);
        }
        __syncthreads();
#pragma unroll
        for (int kk = 0; kk < 16; kk++) {
            float a[8];
#pragma unroll
            for (int i = 0; i < 8; i++) a[i] = As[rg * 8 + i][kk];
            float4 b = Bs[kk][cg];
#pragma unroll
            for (int i = 0; i < 8; i++) {
                acc[i][0] += a[i] * b.x; acc[i][1] += a[i] * b.y;
                acc[i][2] += a[i] * b.z; acc[i][3] += a[i] * b.w;
            }
        }
        __syncthreads();
    }

    float s[4], sh[4], bb[4];
#pragma unroll
    for (int j = 0; j < 4; j++) {
        int c = cg * 4 + j;
        s[j]  = g[c] * rsqrtf(v[c] + EPS);
        sh[j] = be[c] - m[c] * s[j];
        bb[j] = bias[c];
    }
    float fw = FUSEP ? __ldg(sw) : 0.f;
#pragma unroll
    for (int i = 0; i < 8; i++) {
        int rr = rowBase + rg * 8 + i;
        if (rr < M) {
            float4 o;
            o.x = fmaxf((acc[i][0] + bb[0]) * s[0] + sh[0], 0.f);
            o.y = fmaxf((acc[i][1] + bb[1]) * s[1] + sh[1], 0.f);
            o.z = fmaxf((acc[i][2] + bb[2]) * s[2] + sh[2], 0.f);
            o.w = fmaxf((acc[i][3] + bb[3]) * s[3] + sh[3], 0.f);
            if (RES) {
                float4 r4 = *(const float4*)(ident + (size_t)rr * HDIM + cg * 4);
                o.x += r4.x; o.y += r4.y; o.z += r4.z; o.w += r4.w;
            }
            if (FUSEP) {
                __half2 h0 = __floats2half2_rn(o.x, o.y);
                __half2 h1 = __floats2half2_rn(o.z, o.w);
                uint2 hv = make_uint2(*(unsigned*)&h0, *(unsigned*)&h1);
                ((uint2*)(out16 + (size_t)rr * HDIM))[cg] = hv;
                float4 f = make_float4(fw * o.x, fw * o.y, fw * o.z, fw * o.w);
                *(float4*)(F + (size_t)rr * HDIM + cg * 4) = f;
            } else {
                *(float4*)(out32 + (size_t)rr * HDIM + cg * 4) = o;
            }
        }
    }
}

// ---------------------------------------------------------------------------
// CSC build
// ---------------------------------------------------------------------------
__global__ void zero_ws_deg(float* __restrict__ ws, int* __restrict__ deg) {
    int i = blockIdx.x * blockDim.x + threadIdx.x;
    if (i < NNODES) { ws[i] = 0.f; deg[i] = 0; }
}

__global__ void wsum_deg_kernel(const int* __restrict__ row,
                                const int* __restrict__ col,
                                const float* __restrict__ w,
                                float* __restrict__ ws,
                                int* __restrict__ deg) {
    int i = blockIdx.x * blockDim.x + threadIdx.x;
    if (i < NEDGES) {
        atomicAdd(&ws[row[i]], w[i]);
        atomicAdd(&deg[col[i]], 1);
    }
}

__global__ void scan_offsets(const int* __restrict__ deg,
                             int* __restrict__ off,
                             int* __restrict__ cursor) {
    __shared__ int partial[1024];
    const int CH = (NNODES + 1023) / 1024;
    int tid = threadIdx.x;
    int start = tid * CH;
    int sum = 0;
    for (int j = 0; j < CH; j++) {
        int idx = start + j;
        if (idx < NNODES) sum += deg[idx];
    }
    partial[tid] = sum;
    __syncthreads();
    for (int d = 1; d < 1024; d <<= 1) {
        int t = (tid >= d) ? partial[tid - d] : 0;
        __syncthreads();
        partial[tid] += t;
        __syncthreads();
    }
    int run = (tid == 0) ? 0 : partial[tid - 1];
    for (int j = 0; j < CH; j++) {
        int idx = start + j;
        if (idx < NNODES) {
            off[idx] = run;
            cursor[idx] = run;
            run += deg[idx];
        }
    }
    if (tid == 1023) off[NNODES] = NEDGES;
}

__global__ void fill_csc(const int* __restrict__ row,
                         const int* __restrict__ col,
                         const float* __restrict__ w,
                         const float* __restrict__ ws,
                         int* __restrict__ cursor,
                         int2* __restrict__ edge) {
    int i = blockIdx.x * blockDim.x + threadIdx.x;
    if (i < NEDGES) {
        int r = row[i];
        int c = col[i];
        float wn = 0.9f * w[i] / fmaxf(ws[r], 1.0f);
        int pos = atomicAdd(&cursor[c], 1);
        edge[pos] = make_int2(r, __float_as_int(wn));
    }
}

__global__ void softmax6(const float* __restrict__ att, float* __restrict__ sw) {
    if (threadIdx.x == 0 && blockIdx.x == 0) {
        float mx = -1e30f;
        for (int i = 0; i < KHOPS + 1; i++) mx = fmaxf(mx, att[i]);
        float e[KHOPS + 1], sum = 0.f;
        for (int i = 0; i < KHOPS + 1; i++) { e[i] = expf(att[i] - mx); sum += e[i]; }
        for (int i = 0; i < KHOPS + 1; i++) sw[i] = e[i] / sum;
    }
}

// ---------------------------------------------------------------------------
// Propagation gather step — half-warp per edge, LDG.128, fp16 anchor.
// ---------------------------------------------------------------------------
__device__ __forceinline__ void acc8(float* a, uint4 p, float wgt) {
    float2 t0 = __half22float2(*(__half2*)&p.x);
    float2 t1 = __half22float2(*(__half2*)&p.y);
    float2 t2 = __half22float2(*(__half2*)&p.z);
    float2 t3 = __half22float2(*(__half2*)&p.w);
    a[0] += wgt * t0.x; a[1] += wgt * t0.y;
    a[2] += wgt * t1.x; a[3] += wgt * t1.y;
    a[4] += wgt * t2.x; a[5] += wgt * t2.y;
    a[6] += wgt * t3.x; a[7] += wgt * t3.y;
}

template <bool FIN>
__global__ void prop_gather_h(const __half* __restrict__ src16,
                              const __half* __restrict__ anc16,
                              __half* __restrict__ dst16,
                              const int* __restrict__ off,
                              const int2* __restrict__ edge,
                              float* __restrict__ F,
                              const float* __restrict__ sw, int swIdx) {
    int warp = (blockIdx.x * blockDim.x + threadIdx.x) >> 5;
    if (warp >= NNODES) return;
    int lane = threadIdx.x & 31;
    int half = lane >> 4;     // which edge of the pair
    int hl   = lane & 15;     // feature chunk within the row (8 fp16)

    int s = __ldg(off + warp);
    int e = __ldg(off + warp + 1);
    int npair = (e - s + 1) >> 1;

    float a[8];
#pragma unroll
    for (int j = 0; j < 8; j++) a[j] = 0.f;

    int it = 0;
    for (; it + 4 <= npair; it += 4) {
        int b0 = s + 2 * it + half;
        int2 e0 = (b0     < e) ? __ldg(edge + b0)     : make_int2(0, 0);
        int2 e1 = (b0 + 2 < e) ? __ldg(edge + b0 + 2) : make_int2(0, 0);
        int2 e2 = (b0 + 4 < e) ? __ldg(edge + b0 + 4) : make_int2(0, 0);
        int2 e3 = (b0 + 6 < e) ? __ldg(edge + b0 + 6) : make_int2(0, 0);
        uint4 p0 = __ldg((const uint4*)(src16 + (size_t)e0.x * HDIM) + hl);
        uint4 p1 = __ldg((const uint4*)(src16 + (size_t)e1.x * HDIM) + hl);
        uint4 p2 = __ldg((const uint4*)(src16 + (size_t)e2.x * HDIM) + hl);
        uint4 p3 = __ldg((const uint4*)(src16 + (size_t)e3.x * HDIM) + hl);
        acc8(a, p0, __int_as_float(e0.y));
        acc8(a, p1, __int_as_float(e1.y));
        acc8(a, p2, __int_as_float(e2.y));
        acc8(a, p3, __int_as_float(e3.y));
    }
    for (; it < npair; it++) {
        int b0 = s + 2 * it + half;
        int2 e0 = (b0 < e) ? __ldg(edge + b0) : make_int2(0, 0);
        uint4 p0 = __ldg((const uint4*)(src16 + (size_t)e0.x * HDIM) + hl);
        acc8(a, p0, __int_as_float(e0.y));
    }

    // combine the two half-warps (feature chunk hl lives in lanes hl and hl+16)
#pragma unroll
    for (int j = 0; j < 8; j++)
        a[j] += __shfl_down_sync(0xffffffffu, a[j], 16);

    if (half == 0) {
        uint4 hp = __ldg((const uint4*)(anc16 + (size_t)warp * HDIM) + hl);
        float2 h0 = __half22float2(*(__half2*)&hp.x);
        float2 h1 = __half22float2(*(__half2*)&hp.y);
        float2 h2 = __half22float2(*(__half2*)&hp.z);
        float2 h3 = __half22float2(*(__half2*)&hp.w);
        a[0] += 0.1f * h0.x; a[1] += 0.1f * h0.y;
        a[2] += 0.1f * h1.x; a[3] += 0.1f * h1.y;
        a[4] += 0.1f * h2.x; a[5] += 0.1f * h2.y;
        a[6] += 0.1f * h3.x; a[7] += 0.1f * h3.y;

        __half2 o0 = __floats2half2_rn(a[0], a[1]);
        __half2 o1 = __floats2half2_rn(a[2], a[3]);
        __half2 o2 = __floats2half2_rn(a[4], a[5]);
        __half2 o3 = __floats2half2_rn(a[6], a[7]);
        uint4 ov = make_uint4(*(unsigned*)&o0, *(unsigned*)&o1,
                              *(unsigned*)&o2, *(unsigned*)&o3);
        *((uint4*)(dst16 + (size_t)warp * HDIM) + hl) = ov;

        if (FIN) {
            float fw = __ldg(sw + swIdx);
            float4* fp = (float4*)(F + (size_t)warp * HDIM) + hl * 2;
            float4 f0 = fp[0], f1 = fp[1];
            f0.x += fw * a[0]; f0.y += fw * a[1]; f0.z += fw * a[2]; f0.w += fw * a[3];
            f1.x += fw * a[4]; f1.y += fw * a[5]; f1.z += fw * a[6]; f1.w += fw * a[7];
            fp[0] = f0; fp[1] = f1;
        }
    }
}

// ---------------------------------------------------------------------------
// Head: out = relu(bn3(F@W3 + b3)) @ W4 + b4   — one warp per node
// ---------------------------------------------------------------------------
__global__ void head_kernel(const float* __restrict__ F,
                            const float* __restrict__ W3, const float* __restrict__ b3,
                            const float* __restrict__ g3, const float* __restrict__ be3,
                            const float* __restrict__ m3, const float* __restrict__ v3,
                            const float* __restrict__ W4, const float* __restrict__ b4,
                            float* __restrict__ out) {
    __shared__ float sW3[HDIM * H2DIM];
    __shared__ float sW4[H2DIM * ODIM];
    __shared__ float sS3[H2DIM], sSh3[H2DIM], sB4[ODIM];
    __shared__ float fr[8][HDIM];
    __shared__ float hid[8][H2DIM];

    int tid = threadIdx.x;
    for (int i = tid; i < HDIM * H2DIM; i += blockDim.x) sW3[i] = W3[i];
    for (int i = tid; i < H2DIM * ODIM; i += blockDim.x) sW4[i] = W4[i];
    if (tid < H2DIM) {
        float s = g3[tid] * rsqrtf(v3[tid] + EPS);
        sS3[tid] = s;
        sSh3[tid] = (b3[tid] - m3[tid]) * s + be3[tid];
    }
    if (tid < ODIM) sB4[tid] = b4[tid];
    __syncthreads();

    int warp = tid >> 5, lane = tid & 31;
    int nwarps = blockDim.x >> 5;
    for (int n = blockIdx.x * nwarps + warp; n < NNODES; n += gridDim.x * nwarps) {
        ((float4*)fr[warp])[lane] = ((const float4*)(F + (size_t)n * HDIM))[lane];
        __syncwarp();
#pragma unroll
        for (int hh = 0; hh < 2; hh++) {
            int j = lane + 32 * hh;
            float acc = 0.f;
#pragma unroll 8
            for (int k = 0; k < HDIM; k++) acc += fr[warp][k] * sW3[k * H2DIM + j];
            hid[warp][j] = fmaxf(acc * sS3[j] + sSh3[j], 0.f);
        }
        __syncwarp();
        float acc = sB4[lane];
#pragma unroll 8
        for (int j = 0; j < H2DIM; j++) acc += hid[warp][j] * sW4[j * ODIM + lane];
        out[(size_t)n * ODIM + lane] = acc;
        __syncwarp();
    }
}

// ---------------------------------------------------------------------------
// Launch
// ---------------------------------------------------------------------------
extern "C" void kernel_launch(void* const* d_in, const int* in_sizes, int n_in,
                              void* d_out, int out_size) {
    const float* x   = (const float*)d_in[0];
    const int*   ei  = (const int*)d_in[1];
    const float* ew  = (const float*)d_in[2];
    const float* W1  = (const float*)d_in[3];
    const float* b1  = (const float*)d_in[4];
    const float* g1  = (const float*)d_in[5];
    const float* be1 = (const float*)d_in[6];
    const float* m1  = (const float*)d_in[7];
    const float* v1  = (const float*)d_in[8];
    const float* W2  = (const float*)d_in[9];
    const float* b2  = (const float*)d_in[10];
    const float* g2  = (const float*)d_in[11];
    const float* be2 = (const float*)d_in[12];
    const float* m2  = (const float*)d_in[13];
    const float* v2  = (const float*)d_in[14];
    const float* att = (const float*)d_in[15];
    const float* W3  = (const float*)d_in[16];
    const float* b3  = (const float*)d_in[17];
    const float* g3  = (const float*)d_in[18];
    const float* be3 = (const float*)d_in[19];
    const float* m3  = (const float*)d_in[20];
    const float* v3  = (const float*)d_in[21];
    const float* W4  = (const float*)d_in[22];
    const float* b4  = (const float*)d_in[23];

    const int* row = ei;
    const int* col = ei + NEDGES;

    float *B1, *F, *WS, *SW;
    __half* HB[3];
    int *DEG, *CUR, *OFF;
    int2 *EDGE;
    cudaGetSymbolAddress((void**)&B1,    gB1);
    cudaGetSymbolAddress((void**)&F,     gFz);
    cudaGetSymbolAddress((void**)&HB[0], gH0);
    cudaGetSymbolAddress((void**)&HB[1], gH1);
    cudaGetSymbolAddress((void**)&HB[2], gH2);
    cudaGetSymbolAddress((void**)&WS,    gWsum);
    cudaGetSymbolAddress((void**)&DEG,   gDeg);
    cudaGetSymbolAddress((void**)&CUR,   gCur);
    cudaGetSymbolAddress((void**)&OFF,   gOff);
    cudaGetSymbolAddress((void**)&EDGE,  gEdge);
    cudaGetSymbolAddress((void**)&SW,    gSw);

    const int gemmBlocks = (NNODES + 63) / 64;
    const int edgeBlocks = (NEDGES + 255) / 256;
    const int propBlocks = (NNODES * 32 + 255) / 256;

    // Feature MLP. GEMM2 emits fp16 state (buffer 0) + F = sw[0]*hc.
    softmax6<<<1, 32>>>(att, SW);
    gemm_bn_relu<IN_DIM, false, false><<<gemmBlocks, 256>>>(
        x,  W1, b1, g1, be1, m1, v1, nullptr, B1, nullptr, nullptr, nullptr, NNODES);
    gemm_bn_relu<HDIM,   true,  true ><<<gemmBlocks, 256>>>(
        B1, W2, b2, g2, be2, m2, v2, B1, nullptr, HB[0], F, SW, NNODES);

    // CSC build
    zero_ws_deg<<<(NNODES + 255) / 256, 256>>>(WS, DEG);
    wsum_deg_kernel<<<edgeBlocks, 256>>>(row, col, ew, WS, DEG);
    scan_offsets<<<1, 1024>>>(DEG, OFF, CUR);
    fill_csc<<<edgeBlocks, 256>>>(row, col, ew, WS, CUR, EDGE);

    // Propagation: K outer x K inner, 3 rotating fp16 buffers
    int anci = 0, curi = 0;
    for (int k = 0; k < KHOPS; k++) {
        anci = curi;
        for (int t = 0; t < KHOPS; t++) {
            int dsti = 0;
            for (int d = 0; d < 3; d++)
                if (d != anci && d != curi) dsti = d;
            if (t == KHOPS - 1)
                prop_gather_h<true ><<<propBlocks, 256>>>(
                    HB[curi], HB[anci], HB[dsti], OFF, EDGE, F, SW, k + 1);
            else
                prop_gather_h<false><<<propBlocks, 256>>>(
                    HB[curi], HB[anci], HB[dsti], OFF, EDGE, nullptr, SW, 0);
            curi = dsti;
        }
    }

    // Head
    head_kernel<<<1184, 256>>>(F, W3, b3, g3, be3, m3, v3, W4, b4, (float*)d_out);
}